// round 5
// baseline (speedup 1.0000x reference)
#include <cuda_runtime.h>
#include <cuda_fp16.h>
#include <cstdint>

#define MAX_NODES 100000
#define F_DIM     16
#define K_DIM     16
#define OUT_SCALE (1.0f / 128.0f)

// Yh[k][n][16] fp16 (51.2 MB)
__device__ __half g_Yh[(size_t)K_DIM * MAX_NODES * 16];

// ---------- packed fp32x2 helpers (sm_100+ FFMA2) ----------
__device__ __forceinline__ unsigned long long pack2(float a, float b) {
    unsigned long long r;
    asm("mov.b64 %0, {%1, %2};" : "=l"(r) : "f"(a), "f"(b));
    return r;
}
__device__ __forceinline__ void fma2(unsigned long long& d,
                                     unsigned long long a,
                                     unsigned long long b) {
    asm("fma.rn.f32x2 %0, %1, %2, %3;" : "=l"(d) : "l"(a), "l"(b), "l"(d));
}
__device__ __forceinline__ void unpack2(unsigned long long v, float& a, float& b) {
    asm("mov.b64 {%0, %1}, %2;" : "=f"(a), "=f"(b) : "l"(v));
}
__device__ __forceinline__ unsigned h2pack(float lo, float hi) {
    __half2 h = __floats2half2_rn(lo, hi);
    return *reinterpret_cast<unsigned*>(&h);
}
__device__ __forceinline__ float2 h2f(unsigned u) {
    __half2 h = *reinterpret_cast<__half2*>(&u);
    return __half22float2(h);
}

// ============================================================================
// Stage 1: Yh[k][n][:] = x[n] @ W[k].
// Thread = (node, k-quad): 4 k-blocks per thread -> 4x threads vs R3 for
// latency hiding (R4 ncu: occ 33%, issue 28.8% -> grid-limited).
// ============================================================================
__global__ __launch_bounds__(256)
void stage1_kernel(const float* __restrict__ x,
                   const float* __restrict__ W,
                   int n_nodes) {
    __shared__ float Ws[4096];  // 16 KB W[k][i][o]
    for (int idx = threadIdx.x; idx < 4096; idx += 256)
        Ws[idx] = W[idx];
    __syncthreads();

    int gid = blockIdx.x * 256 + threadIdx.x;
    int node = gid >> 2;
    int kq = (gid & 3) * 4;        // k in [kq, kq+4)
    if (node >= n_nodes) return;

    // Load x row (4 threads share the same row -> broadcast-coalesced)
    unsigned long long x2[16];
    const float4* xp = reinterpret_cast<const float4*>(x + (size_t)node * F_DIM);
#pragma unroll
    for (int q = 0; q < 4; q++) {
        float4 v = xp[q];
        x2[4 * q + 0] = pack2(v.x, v.x);
        x2[4 * q + 1] = pack2(v.y, v.y);
        x2[4 * q + 2] = pack2(v.z, v.z);
        x2[4 * q + 3] = pack2(v.w, v.w);
    }

#pragma unroll 1
    for (int kk = 0; kk < 4; kk++) {
        int k = kq + kk;
        unsigned long long acc0 = 0ull, acc1 = 0ull, acc2 = 0ull, acc3 = 0ull;
        unsigned long long acc4 = 0ull, acc5 = 0ull, acc6 = 0ull, acc7 = 0ull;
        const ulonglong2* wbase =
            reinterpret_cast<const ulonglong2*>(Ws + k * 256);
#pragma unroll
        for (int i = 0; i < F_DIM; i++) {
            ulonglong2 wa = wbase[i * 4 + 0];
            ulonglong2 wb = wbase[i * 4 + 1];
            ulonglong2 wc = wbase[i * 4 + 2];
            ulonglong2 wd = wbase[i * 4 + 3];
            unsigned long long xi = x2[i];
            fma2(acc0, xi, wa.x);
            fma2(acc1, xi, wa.y);
            fma2(acc2, xi, wb.x);
            fma2(acc3, xi, wb.y);
            fma2(acc4, xi, wc.x);
            fma2(acc5, xi, wc.y);
            fma2(acc6, xi, wd.x);
            fma2(acc7, xi, wd.y);
        }
        float o0, o1, o2, o3, o4, o5, o6, o7;
        float o8, o9, oa, ob, oc, od, oe, of_;
        unpack2(acc0, o0, o1); unpack2(acc1, o2, o3);
        unpack2(acc2, o4, o5); unpack2(acc3, o6, o7);
        unpack2(acc4, o8, o9); unpack2(acc5, oa, ob);
        unpack2(acc6, oc, od); unpack2(acc7, oe, of_);

        uint4 s0, s1;
        s0.x = h2pack(o0, o1); s0.y = h2pack(o2, o3);
        s0.z = h2pack(o4, o5); s0.w = h2pack(o6, o7);
        s1.x = h2pack(o8, o9); s1.y = h2pack(oa, ob);
        s1.z = h2pack(oc, od); s1.w = h2pack(oe, of_);

        uint4* yo = reinterpret_cast<uint4*>(
            g_Yh + ((size_t)k * n_nodes + node) * 16);
        yo[0] = s0;
        yo[1] = s1;
    }
}

// ============================================================================
// Stage 2: per edge — bilinear combine of 4 fp16 Y blocks + atomic scatter
// (identical to R3's 43.2us kernel)
// ============================================================================
__global__ __launch_bounds__(256)
void stage2_kernel(const float2* __restrict__ edge_attr,
                   const int* __restrict__ ei,
                   const int* __restrict__ ej,
                   float* __restrict__ out,
                   int n_nodes, int n_edges) {
    int e = blockIdx.x * 256 + threadIdx.x;
    if (e >= n_edges) return;

    int di = ei[e];
    int dj = ej[e];
    if (di == dj) return;  // centerIgnore

    float2 at = edge_attr[e];
    float ux = fminf(fmaxf(at.x, -1.0f), 1.0f);
    float uy = fminf(fmaxf(at.y, -1.0f), 1.0f);
    float vx = (ux + 1.0f) * 1.5f;
    float vy = (uy + 1.0f) * 1.5f;
    int a = min((int)vx, 2);
    int b = min((int)vy, 2);
    float s = vx - (float)a;
    float t = vy - (float)b;

    float c00 = (1.0f - s) * (1.0f - t) * OUT_SCALE;
    float c01 = (1.0f - s) * t * OUT_SCALE;
    float c10 = s * (1.0f - t) * OUT_SCALE;
    float c11 = s * t * OUT_SCALE;

    int k00 = a * 4 + b;
    size_t row = (size_t)dj * 16;
    size_t kstride = (size_t)n_nodes * 16;
    const uint4* pA = reinterpret_cast<const uint4*>(g_Yh + (size_t)k00 * kstride + row);
    const uint4* pB = reinterpret_cast<const uint4*>(g_Yh + (size_t)(k00 + 1) * kstride + row);
    const uint4* pC = reinterpret_cast<const uint4*>(g_Yh + (size_t)(k00 + 4) * kstride + row);
    const uint4* pD = reinterpret_cast<const uint4*>(g_Yh + (size_t)(k00 + 5) * kstride + row);

    uint4 A0 = pA[0], A1 = pA[1];
    uint4 B0 = pB[0], B1 = pB[1];
    uint4 C0 = pC[0], C1 = pC[1];
    uint4 D0 = pD[0], D1 = pD[1];

    float* obase = out + (size_t)di * 16;

    {
        float2 fA, fB, fC, fD, m01, m23, m45, m67;
        fA = h2f(A0.x); fB = h2f(B0.x); fC = h2f(C0.x); fD = h2f(D0.x);
        m01.x = c00*fA.x + c01*fB.x + c10*fC.x + c11*fD.x;
        m01.y = c00*fA.y + c01*fB.y + c10*fC.y + c11*fD.y;
        fA = h2f(A0.y); fB = h2f(B0.y); fC = h2f(C0.y); fD = h2f(D0.y);
        m23.x = c00*fA.x + c01*fB.x + c10*fC.x + c11*fD.x;
        m23.y = c00*fA.y + c01*fB.y + c10*fC.y + c11*fD.y;
        fA = h2f(A0.z); fB = h2f(B0.z); fC = h2f(C0.z); fD = h2f(D0.z);
        m45.x = c00*fA.x + c01*fB.x + c10*fC.x + c11*fD.x;
        m45.y = c00*fA.y + c01*fB.y + c10*fC.y + c11*fD.y;
        fA = h2f(A0.w); fB = h2f(B0.w); fC = h2f(C0.w); fD = h2f(D0.w);
        m67.x = c00*fA.x + c01*fB.x + c10*fC.x + c11*fD.x;
        m67.y = c00*fA.y + c01*fB.y + c10*fC.y + c11*fD.y;
        asm volatile("red.global.add.v4.f32 [%0], {%1, %2, %3, %4};"
                     :: "l"(obase + 0), "f"(m01.x), "f"(m01.y), "f"(m23.x), "f"(m23.y)
                     : "memory");
        asm volatile("red.global.add.v4.f32 [%0], {%1, %2, %3, %4};"
                     :: "l"(obase + 4), "f"(m45.x), "f"(m45.y), "f"(m67.x), "f"(m67.y)
                     : "memory");
    }
    {
        float2 fA, fB, fC, fD, m01, m23, m45, m67;
        fA = h2f(A1.x); fB = h2f(B1.x); fC = h2f(C1.x); fD = h2f(D1.x);
        m01.x = c00*fA.x + c01*fB.x + c10*fC.x + c11*fD.x;
        m01.y = c00*fA.y + c01*fB.y + c10*fC.y + c11*fD.y;
        fA = h2f(A1.y); fB = h2f(B1.y); fC = h2f(C1.y); fD = h2f(D1.y);
        m23.x = c00*fA.x + c01*fB.x + c10*fC.x + c11*fD.x;
        m23.y = c00*fA.y + c01*fB.y + c10*fC.y + c11*fD.y;
        fA = h2f(A1.z); fB = h2f(B1.z); fC = h2f(C1.z); fD = h2f(D1.z);
        m45.x = c00*fA.x + c01*fB.x + c10*fC.x + c11*fD.x;
        m45.y = c00*fA.y + c01*fB.y + c10*fC.y + c11*fD.y;
        fA = h2f(A1.w); fB = h2f(B1.w); fC = h2f(C1.w); fD = h2f(D1.w);
        m67.x = c00*fA.x + c01*fB.x + c10*fC.x + c11*fD.x;
        m67.y = c00*fA.y + c01*fB.y + c10*fC.y + c11*fD.y;
        asm volatile("red.global.add.v4.f32 [%0], {%1, %2, %3, %4};"
                     :: "l"(obase + 8), "f"(m01.x), "f"(m01.y), "f"(m23.x), "f"(m23.y)
                     : "memory");
        asm volatile("red.global.add.v4.f32 [%0], {%1, %2, %3, %4};"
                     :: "l"(obase + 12), "f"(m45.x), "f"(m45.y), "f"(m67.x), "f"(m67.y)
                     : "memory");
    }
}

extern "C" void kernel_launch(void* const* d_in, const int* in_sizes, int n_in,
                              void* d_out, int out_size) {
    const float*  x  = (const float*)d_in[0];    // [N, 16] f32
    const float2* ea = (const float2*)d_in[1];   // [E, 2]  f32
    const float*  W  = (const float*)d_in[2];    // [16,16,16] f32
    const int*    ei = (const int*)d_in[3];      // [E] int32
    const int*    ej = (const int*)d_in[4];      // [E] int32
    float* out = (float*)d_out;

    int n_nodes = in_sizes[0] / F_DIM;
    int n_edges = in_sizes[1] / 2;

    cudaMemsetAsync(d_out, 0, (size_t)out_size * sizeof(float), 0);

    int s1_threads = n_nodes * 4;
    stage1_kernel<<<(s1_threads + 255) / 256, 256>>>(x, W, n_nodes);
    stage2_kernel<<<(n_edges + 255) / 256, 256>>>(ea, ei, ej, out, n_nodes, n_edges);
}

// round 6
// speedup vs baseline: 2.8086x; 2.8086x over previous
#include <cuda_runtime.h>
#include <cuda_fp16.h>
#include <cstdint>

#define MAX_NODES 100000
#define F_DIM     16
#define K_DIM     16
#define OUT_SCALE (1.0f / 128.0f)

// Yh[k][n][16] fp16 (51.2 MB)
__device__ __half g_Yh[(size_t)K_DIM * MAX_NODES * 16];

// ---------- packed fp32x2 helpers (sm_100+ FFMA2) ----------
__device__ __forceinline__ unsigned long long pack2(float a, float b) {
    unsigned long long r;
    asm("mov.b64 %0, {%1, %2};" : "=l"(r) : "f"(a), "f"(b));
    return r;
}
__device__ __forceinline__ void fma2(unsigned long long& d,
                                     unsigned long long a,
                                     unsigned long long b) {
    asm("fma.rn.f32x2 %0, %1, %2, %3;" : "=l"(d) : "l"(a), "l"(b), "l"(d));
}
__device__ __forceinline__ void unpack2(unsigned long long v, float& a, float& b) {
    asm("mov.b64 {%0, %1}, %2;" : "=f"(a), "=f"(b) : "l"(v));
}
__device__ __forceinline__ unsigned h2pack(float lo, float hi) {
    __half2 h = __floats2half2_rn(lo, hi);
    return *reinterpret_cast<unsigned*>(&h);
}
__device__ __forceinline__ float2 h2f(unsigned u) {
    __half2 h = *reinterpret_cast<__half2*>(&u);
    return __half22float2(h);
}

// ============================================================================
// Stage 1: Yh[k][n][:] = x[n] @ W[k].
// Grid: (node_tiles, 4). blockIdx.y selects a k-quad -> k is BLOCK-uniform,
// so all W smem reads are warp-uniform broadcasts (R5's lane-varying kq
// caused 4-way same-bank LDS conflicts -> 5x regression; fixed here).
// 4x blocks vs R3/R4 for latency hiding (R4: occ 33%, issue 28.8%).
// ============================================================================
__global__ __launch_bounds__(256)
void stage1_kernel(const float* __restrict__ x,
                   const float* __restrict__ W,
                   int n_nodes) {
    __shared__ float Ws[4096];  // full W (16 KB); only 4 KB used per block
    for (int idx = threadIdx.x; idx < 4096; idx += 256)
        Ws[idx] = W[idx];
    __syncthreads();

    int node = blockIdx.x * 256 + threadIdx.x;
    int kq = blockIdx.y * 4;       // block-uniform k-quad
    if (node >= n_nodes) return;

    unsigned long long x2[16];
    const float4* xp = reinterpret_cast<const float4*>(x + (size_t)node * F_DIM);
#pragma unroll
    for (int q = 0; q < 4; q++) {
        float4 v = xp[q];
        x2[4 * q + 0] = pack2(v.x, v.x);
        x2[4 * q + 1] = pack2(v.y, v.y);
        x2[4 * q + 2] = pack2(v.z, v.z);
        x2[4 * q + 3] = pack2(v.w, v.w);
    }

#pragma unroll 1
    for (int kk = 0; kk < 4; kk++) {
        int k = kq + kk;
        unsigned long long acc0 = 0ull, acc1 = 0ull, acc2 = 0ull, acc3 = 0ull;
        unsigned long long acc4 = 0ull, acc5 = 0ull, acc6 = 0ull, acc7 = 0ull;
        const ulonglong2* wbase =
            reinterpret_cast<const ulonglong2*>(Ws + k * 256);
#pragma unroll
        for (int i = 0; i < F_DIM; i++) {
            ulonglong2 wa = wbase[i * 4 + 0];
            ulonglong2 wb = wbase[i * 4 + 1];
            ulonglong2 wc = wbase[i * 4 + 2];
            ulonglong2 wd = wbase[i * 4 + 3];
            unsigned long long xi = x2[i];
            fma2(acc0, xi, wa.x);
            fma2(acc1, xi, wa.y);
            fma2(acc2, xi, wb.x);
            fma2(acc3, xi, wb.y);
            fma2(acc4, xi, wc.x);
            fma2(acc5, xi, wc.y);
            fma2(acc6, xi, wd.x);
            fma2(acc7, xi, wd.y);
        }
        float o0, o1, o2, o3, o4, o5, o6, o7;
        float o8, o9, oa, ob, oc, od, oe, of_;
        unpack2(acc0, o0, o1); unpack2(acc1, o2, o3);
        unpack2(acc2, o4, o5); unpack2(acc3, o6, o7);
        unpack2(acc4, o8, o9); unpack2(acc5, oa, ob);
        unpack2(acc6, oc, od); unpack2(acc7, oe, of_);

        uint4 s0, s1;
        s0.x = h2pack(o0, o1); s0.y = h2pack(o2, o3);
        s0.z = h2pack(o4, o5); s0.w = h2pack(o6, o7);
        s1.x = h2pack(o8, o9); s1.y = h2pack(oa, ob);
        s1.z = h2pack(oc, od); s1.w = h2pack(oe, of_);

        uint4* yo = reinterpret_cast<uint4*>(
            g_Yh + ((size_t)k * n_nodes + node) * 16);
        yo[0] = s0;
        yo[1] = s1;
    }
}

// ============================================================================
// Stage 2: per edge — bilinear combine of 4 fp16 Y blocks + atomic scatter
// (identical to R3's 43.2us kernel)
// ============================================================================
__global__ __launch_bounds__(256)
void stage2_kernel(const float2* __restrict__ edge_attr,
                   const int* __restrict__ ei,
                   const int* __restrict__ ej,
                   float* __restrict__ out,
                   int n_nodes, int n_edges) {
    int e = blockIdx.x * 256 + threadIdx.x;
    if (e >= n_edges) return;

    int di = ei[e];
    int dj = ej[e];
    if (di == dj) return;  // centerIgnore

    float2 at = edge_attr[e];
    float ux = fminf(fmaxf(at.x, -1.0f), 1.0f);
    float uy = fminf(fmaxf(at.y, -1.0f), 1.0f);
    float vx = (ux + 1.0f) * 1.5f;
    float vy = (uy + 1.0f) * 1.5f;
    int a = min((int)vx, 2);
    int b = min((int)vy, 2);
    float s = vx - (float)a;
    float t = vy - (float)b;

    float c00 = (1.0f - s) * (1.0f - t) * OUT_SCALE;
    float c01 = (1.0f - s) * t * OUT_SCALE;
    float c10 = s * (1.0f - t) * OUT_SCALE;
    float c11 = s * t * OUT_SCALE;

    int k00 = a * 4 + b;
    size_t row = (size_t)dj * 16;
    size_t kstride = (size_t)n_nodes * 16;
    const uint4* pA = reinterpret_cast<const uint4*>(g_Yh + (size_t)k00 * kstride + row);
    const uint4* pB = reinterpret_cast<const uint4*>(g_Yh + (size_t)(k00 + 1) * kstride + row);
    const uint4* pC = reinterpret_cast<const uint4*>(g_Yh + (size_t)(k00 + 4) * kstride + row);
    const uint4* pD = reinterpret_cast<const uint4*>(g_Yh + (size_t)(k00 + 5) * kstride + row);

    uint4 A0 = pA[0], A1 = pA[1];
    uint4 B0 = pB[0], B1 = pB[1];
    uint4 C0 = pC[0], C1 = pC[1];
    uint4 D0 = pD[0], D1 = pD[1];

    float* obase = out + (size_t)di * 16;

    {
        float2 fA, fB, fC, fD, m01, m23, m45, m67;
        fA = h2f(A0.x); fB = h2f(B0.x); fC = h2f(C0.x); fD = h2f(D0.x);
        m01.x = c00*fA.x + c01*fB.x + c10*fC.x + c11*fD.x;
        m01.y = c00*fA.y + c01*fB.y + c10*fC.y + c11*fD.y;
        fA = h2f(A0.y); fB = h2f(B0.y); fC = h2f(C0.y); fD = h2f(D0.y);
        m23.x = c00*fA.x + c01*fB.x + c10*fC.x + c11*fD.x;
        m23.y = c00*fA.y + c01*fB.y + c10*fC.y + c11*fD.y;
        fA = h2f(A0.z); fB = h2f(B0.z); fC = h2f(C0.z); fD = h2f(D0.z);
        m45.x = c00*fA.x + c01*fB.x + c10*fC.x + c11*fD.x;
        m45.y = c00*fA.y + c01*fB.y + c10*fC.y + c11*fD.y;
        fA = h2f(A0.w); fB = h2f(B0.w); fC = h2f(C0.w); fD = h2f(D0.w);
        m67.x = c00*fA.x + c01*fB.x + c10*fC.x + c11*fD.x;
        m67.y = c00*fA.y + c01*fB.y + c10*fC.y + c11*fD.y;
        asm volatile("red.global.add.v4.f32 [%0], {%1, %2, %3, %4};"
                     :: "l"(obase + 0), "f"(m01.x), "f"(m01.y), "f"(m23.x), "f"(m23.y)
                     : "memory");
        asm volatile("red.global.add.v4.f32 [%0], {%1, %2, %3, %4};"
                     :: "l"(obase + 4), "f"(m45.x), "f"(m45.y), "f"(m67.x), "f"(m67.y)
                     : "memory");
    }
    {
        float2 fA, fB, fC, fD, m01, m23, m45, m67;
        fA = h2f(A1.x); fB = h2f(B1.x); fC = h2f(C1.x); fD = h2f(D1.x);
        m01.x = c00*fA.x + c01*fB.x + c10*fC.x + c11*fD.x;
        m01.y = c00*fA.y + c01*fB.y + c10*fC.y + c11*fD.y;
        fA = h2f(A1.y); fB = h2f(B1.y); fC = h2f(C1.y); fD = h2f(D1.y);
        m23.x = c00*fA.x + c01*fB.x + c10*fC.x + c11*fD.x;
        m23.y = c00*fA.y + c01*fB.y + c10*fC.y + c11*fD.y;
        fA = h2f(A1.z); fB = h2f(B1.z); fC = h2f(C1.z); fD = h2f(D1.z);
        m45.x = c00*fA.x + c01*fB.x + c10*fC.x + c11*fD.x;
        m45.y = c00*fA.y + c01*fB.y + c10*fC.y + c11*fD.y;
        fA = h2f(A1.w); fB = h2f(B1.w); fC = h2f(C1.w); fD = h2f(D1.w);
        m67.x = c00*fA.x + c01*fB.x + c10*fC.x + c11*fD.x;
        m67.y = c00*fA.y + c01*fB.y + c10*fC.y + c11*fD.y;
        asm volatile("red.global.add.v4.f32 [%0], {%1, %2, %3, %4};"
                     :: "l"(obase + 8), "f"(m01.x), "f"(m01.y), "f"(m23.x), "f"(m23.y)
                     : "memory");
        asm volatile("red.global.add.v4.f32 [%0], {%1, %2, %3, %4};"
                     :: "l"(obase + 12), "f"(m45.x), "f"(m45.y), "f"(m67.x), "f"(m67.y)
                     : "memory");
    }
}

extern "C" void kernel_launch(void* const* d_in, const int* in_sizes, int n_in,
                              void* d_out, int out_size) {
    const float*  x  = (const float*)d_in[0];    // [N, 16] f32
    const float2* ea = (const float2*)d_in[1];   // [E, 2]  f32
    const float*  W  = (const float*)d_in[2];    // [16,16,16] f32
    const int*    ei = (const int*)d_in[3];      // [E] int32
    const int*    ej = (const int*)d_in[4];      // [E] int32
    float* out = (float*)d_out;

    int n_nodes = in_sizes[0] / F_DIM;
    int n_edges = in_sizes[1] / 2;

    cudaMemsetAsync(d_out, 0, (size_t)out_size * sizeof(float), 0);

    dim3 s1grid((n_nodes + 255) / 256, 4);
    stage1_kernel<<<s1grid, 256>>>(x, W, n_nodes);
    stage2_kernel<<<(n_edges + 255) / 256, 256>>>(ea, ei, ej, out, n_nodes, n_edges);
}

// round 7
// speedup vs baseline: 2.8722x; 1.0226x over previous
#include <cuda_runtime.h>
#include <cuda_fp16.h>
#include <cstdint>

#define MAX_NODES 100000
#define F_DIM     16
#define K_DIM     16
#define OUT_SCALE (1.0f / 128.0f)

// Yh[k][n][16] fp16 (51.2 MB)
__device__ __half g_Yh[(size_t)K_DIM * MAX_NODES * 16];

typedef unsigned long long ull;

// ---------- packed fp32x2 helpers (sm_100+ FFMA2) ----------
__device__ __forceinline__ ull pack2(float a, float b) {
    ull r;
    asm("mov.b64 %0, {%1, %2};" : "=l"(r) : "f"(a), "f"(b));
    return r;
}
__device__ __forceinline__ void fma2(ull& d, ull a, ull b) {
    asm("fma.rn.f32x2 %0, %1, %2, %3;" : "=l"(d) : "l"(a), "l"(b), "l"(d));
}
__device__ __forceinline__ void unpack2(ull v, float& a, float& b) {
    asm("mov.b64 {%0, %1}, %2;" : "=f"(a), "=f"(b) : "l"(v));
}
__device__ __forceinline__ float2 h2f(unsigned u) {
    __half2 h = *reinterpret_cast<__half2*>(&u);
    return __half22float2(h);
}

// ============================================================================
// Stage 1 (register-tiled GEMM): C[N,256] = X[N,16] @ Wm[16,256],
// Wm[i][k*16+o] = W[k][i][o].  Block = 64 nodes x 256 outputs, 256 threads.
// Thread (og=tid&31, ng=tid>>5) computes 8 nodes x 4 output-PAIRS
// (j-pairs p = og+32c, j=2p). Per i: 8 uniform x LDS.64 + 4 coalesced w
// LDS.64 + 32 FFMA2 -> ~8x less logical smem traffic than the broadcast
// kernel (R4/R6: W broadcast paid 32-lane wavefront bytes -> 38us wall).
// ============================================================================
__global__ __launch_bounds__(256)
void stage1_kernel(const float* __restrict__ x,
                   const float* __restrict__ W,
                   int n_nodes) {
    __shared__ ull ws2[16 * 128];  // 16 KB: ws2[i][p] = (Wm[i][2p], Wm[i][2p+1])
    __shared__ ull xs2[64 * 16];   //  8 KB: xs2[n][i] = (x[n][i], x[n][i])

    int tid = threadIdx.x;
    int node_base = blockIdx.x * 64;

    // Build ws2: p = k*8 + o/2 (o even); W linear = k*256 + i*16 + o
    for (int idx = tid; idx < 2048; idx += 256) {
        int i = idx >> 7;
        int p = idx & 127;
        int k = p >> 3;
        int o = (p & 7) << 1;
        const float2 w = *reinterpret_cast<const float2*>(
            W + k * 256 + i * 16 + o);
        ws2[idx] = pack2(w.x, w.y);
    }
    // Build xs2 (clamp node for the partial last block; stores are guarded)
    for (int idx = tid; idx < 1024; idx += 256) {
        int n = idx >> 4;
        int i = idx & 15;
        int node = node_base + n;
        if (node >= n_nodes) node = n_nodes - 1;
        float v = x[(size_t)node * F_DIM + i];
        xs2[idx] = pack2(v, v);
    }
    __syncthreads();

    int og = tid & 31;   // output-pair group
    int ng = tid >> 5;   // node group (warp-uniform)

    ull acc[8][4];
#pragma unroll
    for (int n = 0; n < 8; n++)
#pragma unroll
        for (int c = 0; c < 4; c++) acc[n][c] = 0ull;

    const ull* xbase = xs2 + (ng * 8) * 16;
    const ull* wrow = ws2 + og;

#pragma unroll 4
    for (int i = 0; i < F_DIM; i++) {
        ull w0 = wrow[i * 128 + 0];
        ull w1 = wrow[i * 128 + 32];
        ull w2 = wrow[i * 128 + 64];
        ull w3 = wrow[i * 128 + 96];
#pragma unroll
        for (int n = 0; n < 8; n++) {
            ull xq = xbase[n * 16 + i];   // warp-uniform broadcast
            fma2(acc[n][0], xq, w0);
            fma2(acc[n][1], xq, w1);
            fma2(acc[n][2], xq, w2);
            fma2(acc[n][3], xq, w3);
        }
    }

    // Store: j-pair p = og + 32c -> k = og/8 + 4c, o = 2*(og&7).
    // Warp store pattern per (n,c): 4 distinct k-rows x 32B contiguous.
    int o = (og & 7) << 1;
    int kbase = og >> 3;
#pragma unroll
    for (int n = 0; n < 8; n++) {
        int node = node_base + ng * 8 + n;
        if (node >= n_nodes) break;
#pragma unroll
        for (int c = 0; c < 4; c++) {
            int k = kbase + 4 * c;
            float lo, hi;
            unpack2(acc[n][c], lo, hi);
            __half2 h = __floats2half2_rn(lo, hi);
            *reinterpret_cast<unsigned*>(
                g_Yh + ((size_t)k * n_nodes + node) * 16 + o) =
                *reinterpret_cast<unsigned*>(&h);
        }
    }
}

// ============================================================================
// Stage 2: per edge — bilinear combine of 4 fp16 Y blocks + atomic scatter
// (identical to the 42.4us kernel)
// ============================================================================
__global__ __launch_bounds__(256)
void stage2_kernel(const float2* __restrict__ edge_attr,
                   const int* __restrict__ ei,
                   const int* __restrict__ ej,
                   float* __restrict__ out,
                   int n_nodes, int n_edges) {
    int e = blockIdx.x * 256 + threadIdx.x;
    if (e >= n_edges) return;

    int di = ei[e];
    int dj = ej[e];
    if (di == dj) return;  // centerIgnore

    float2 at = edge_attr[e];
    float ux = fminf(fmaxf(at.x, -1.0f), 1.0f);
    float uy = fminf(fmaxf(at.y, -1.0f), 1.0f);
    float vx = (ux + 1.0f) * 1.5f;
    float vy = (uy + 1.0f) * 1.5f;
    int a = min((int)vx, 2);
    int b = min((int)vy, 2);
    float s = vx - (float)a;
    float t = vy - (float)b;

    float c00 = (1.0f - s) * (1.0f - t) * OUT_SCALE;
    float c01 = (1.0f - s) * t * OUT_SCALE;
    float c10 = s * (1.0f - t) * OUT_SCALE;
    float c11 = s * t * OUT_SCALE;

    int k00 = a * 4 + b;
    size_t row = (size_t)dj * 16;
    size_t kstride = (size_t)n_nodes * 16;
    const uint4* pA = reinterpret_cast<const uint4*>(g_Yh + (size_t)k00 * kstride + row);
    const uint4* pB = reinterpret_cast<const uint4*>(g_Yh + (size_t)(k00 + 1) * kstride + row);
    const uint4* pC = reinterpret_cast<const uint4*>(g_Yh + (size_t)(k00 + 4) * kstride + row);
    const uint4* pD = reinterpret_cast<const uint4*>(g_Yh + (size_t)(k00 + 5) * kstride + row);

    uint4 A0 = pA[0], A1 = pA[1];
    uint4 B0 = pB[0], B1 = pB[1];
    uint4 C0 = pC[0], C1 = pC[1];
    uint4 D0 = pD[0], D1 = pD[1];

    float* obase = out + (size_t)di * 16;

    {
        float2 fA, fB, fC, fD, m01, m23, m45, m67;
        fA = h2f(A0.x); fB = h2f(B0.x); fC = h2f(C0.x); fD = h2f(D0.x);
        m01.x = c00*fA.x + c01*fB.x + c10*fC.x + c11*fD.x;
        m01.y = c00*fA.y + c01*fB.y + c10*fC.y + c11*fD.y;
        fA = h2f(A0.y); fB = h2f(B0.y); fC = h2f(C0.y); fD = h2f(D0.y);
        m23.x = c00*fA.x + c01*fB.x + c10*fC.x + c11*fD.x;
        m23.y = c00*fA.y + c01*fB.y + c10*fC.y + c11*fD.y;
        fA = h2f(A0.z); fB = h2f(B0.z); fC = h2f(C0.z); fD = h2f(D0.z);
        m45.x = c00*fA.x + c01*fB.x + c10*fC.x + c11*fD.x;
        m45.y = c00*fA.y + c01*fB.y + c10*fC.y + c11*fD.y;
        fA = h2f(A0.w); fB = h2f(B0.w); fC = h2f(C0.w); fD = h2f(D0.w);
        m67.x = c00*fA.x + c01*fB.x + c10*fC.x + c11*fD.x;
        m67.y = c00*fA.y + c01*fB.y + c10*fC.y + c11*fD.y;
        asm volatile("red.global.add.v4.f32 [%0], {%1, %2, %3, %4};"
                     :: "l"(obase + 0), "f"(m01.x), "f"(m01.y), "f"(m23.x), "f"(m23.y)
                     : "memory");
        asm volatile("red.global.add.v4.f32 [%0], {%1, %2, %3, %4};"
                     :: "l"(obase + 4), "f"(m45.x), "f"(m45.y), "f"(m67.x), "f"(m67.y)
                     : "memory");
    }
    {
        float2 fA, fB, fC, fD, m01, m23, m45, m67;
        fA = h2f(A1.x); fB = h2f(B1.x); fC = h2f(C1.x); fD = h2f(D1.x);
        m01.x = c00*fA.x + c01*fB.x + c10*fC.x + c11*fD.x;
        m01.y = c00*fA.y + c01*fB.y + c10*fC.y + c11*fD.y;
        fA = h2f(A1.y); fB = h2f(B1.y); fC = h2f(C1.y); fD = h2f(D1.y);
        m23.x = c00*fA.x + c01*fB.x + c10*fC.x + c11*fD.x;
        m23.y = c00*fA.y + c01*fB.y + c10*fC.y + c11*fD.y;
        fA = h2f(A1.z); fB = h2f(B1.z); fC = h2f(C1.z); fD = h2f(D1.z);
        m45.x = c00*fA.x + c01*fB.x + c10*fC.x + c11*fD.x;
        m45.y = c00*fA.y + c01*fB.y + c10*fC.y + c11*fD.y;
        fA = h2f(A1.w); fB = h2f(B1.w); fC = h2f(C1.w); fD = h2f(D1.w);
        m67.x = c00*fA.x + c01*fB.x + c10*fC.x + c11*fD.x;
        m67.y = c00*fA.y + c01*fB.y + c10*fC.y + c11*fD.y;
        asm volatile("red.global.add.v4.f32 [%0], {%1, %2, %3, %4};"
                     :: "l"(obase + 8), "f"(m01.x), "f"(m01.y), "f"(m23.x), "f"(m23.y)
                     : "memory");
        asm volatile("red.global.add.v4.f32 [%0], {%1, %2, %3, %4};"
                     :: "l"(obase + 12), "f"(m45.x), "f"(m45.y), "f"(m67.x), "f"(m67.y)
                     : "memory");
    }
}

extern "C" void kernel_launch(void* const* d_in, const int* in_sizes, int n_in,
                              void* d_out, int out_size) {
    const float*  x  = (const float*)d_in[0];    // [N, 16] f32
    const float2* ea = (const float2*)d_in[1];   // [E, 2]  f32
    const float*  W  = (const float*)d_in[2];    // [16,16,16] f32
    const int*    ei = (const int*)d_in[3];      // [E] int32
    const int*    ej = (const int*)d_in[4];      // [E] int32
    float* out = (float*)d_out;

    int n_nodes = in_sizes[0] / F_DIM;
    int n_edges = in_sizes[1] / 2;

    cudaMemsetAsync(d_out, 0, (size_t)out_size * sizeof(float), 0);

    stage1_kernel<<<(n_nodes + 63) / 64, 256>>>(x, W, n_nodes);
    stage2_kernel<<<(n_edges + 255) / 256, 256>>>(ea, ei, ej, out, n_nodes, n_edges);
}